// round 12
// baseline (speedup 1.0000x reference)
#include <cuda_runtime.h>
#include <cuda_fp16.h>
#include <cstdint>

#define NN   50000
#define EE   800000
#define DINN 128
#define DHH  256
#define DOUTT 64
#define GGG  64
#define TOTE (EE + NN)
#define NCHUNK 49   // ceil(NN/1024)

// ---------------- scratch (static device globals) ---------------------------
__device__ __align__(16) __half g_hh[(size_t)NN * DHH]; // GEMM output h (fp16)
__device__ __align__(16) float g_f[(size_t)NN * DHH];   // aggregated (last layer, for pool)
__device__ __align__(16) __half g_ah[(size_t)NN * DHH]; // A hi (fp16)
__device__ __align__(16) __half g_al[(size_t)NN * DHH]; // A lo (fp16)
__device__ __align__(16) __half g_bh[DHH * DHH];        // Wt fp16 [256][K]
__device__ float g_sv[NN];
__device__ float g_dv[NN];
__device__ float2 g_stat[NN];   // per-node (softmax max, 1/denominator)
__device__ float g_pool[GGG * DHH];
__device__ int   g_cnt[NN];
__device__ int   g_rowptr[NN + 1];
__device__ int   g_cur[NN];
__device__ int   g_col[TOTE];
__device__ int   g_csum[NCHUNK];
__device__ int   g_i32;      // 1 => index tensors are int32, 0 => int64

// ---------------- dtype-agnostic index load ---------------------------------
__device__ __forceinline__ int ld_idx(const void* p, long i) {
    return g_i32 ? ((const int*)p)[i] : (int)((const long long*)p)[i];
}

__global__ void k_detect(const int* __restrict__ ei32) {
    __shared__ int any;
    if (threadIdx.x == 0) any = 0;
    __syncthreads();
    if (ei32[2 * threadIdx.x + 1] != 0) atomicOr(&any, 1);
    __syncthreads();
    if (threadIdx.x == 0) g_i32 = any;
}

// ---------------- CSR build -------------------------------------------------
__global__ void k_init_cnt() {
    int i = blockIdx.x * blockDim.x + threadIdx.x;
    if (i < NN) g_cnt[i] = 1;   // self-loop
}

__global__ void k_hist(const void* __restrict__ ei) {
    int e = blockIdx.x * blockDim.x + threadIdx.x;
    if (e < EE) atomicAdd(&g_cnt[ld_idx(ei, (long)EE + e)], 1);
}

__global__ void k_chunk_sum() {
    __shared__ int sr[1024];
    int tid = threadIdx.x;
    int i = blockIdx.x * 1024 + tid;
    sr[tid] = (i < NN) ? g_cnt[i] : 0;
    __syncthreads();
    for (int off = 512; off; off >>= 1) {
        if (tid < off) sr[tid] += sr[tid + off];
        __syncthreads();
    }
    if (tid == 0) g_csum[blockIdx.x] = sr[0];
}

__global__ void k_scan_chunks() {
    int run = 0;
    for (int c = 0; c < NCHUNK; c++) {
        int t = g_csum[c];
        g_csum[c] = run;
        run += t;
    }
    g_rowptr[NN] = TOTE;
}

__global__ void k_local_scan() {
    __shared__ int ss[1024];
    int tid = threadIdx.x;
    int i = blockIdx.x * 1024 + tid;
    int v = (i < NN) ? g_cnt[i] : 0;
    ss[tid] = v;
    __syncthreads();
    for (int off = 1; off < 1024; off <<= 1) {
        int add = (tid >= off) ? ss[tid - off] : 0;
        __syncthreads();
        ss[tid] += add;
        __syncthreads();
    }
    if (i < NN) {
        int rp = g_csum[blockIdx.x] + ss[tid] - v;   // exclusive
        g_rowptr[i] = rp;
        g_cur[i] = rp;
    }
}

__global__ void k_scatter(const void* __restrict__ ei) {
    int idx = blockIdx.x * blockDim.x + threadIdx.x;
    if (idx < GGG * DHH) g_pool[idx] = 0.f;     // fold pool zeroing in
    if (idx < EE) {
        int src = ld_idx(ei, idx);
        int dst = ld_idx(ei, (long)EE + idx);
        int pos = atomicAdd(&g_cur[dst], 1);
        g_col[pos] = src;
    } else if (idx < TOTE) {
        int i = idx - EE;
        int pos = atomicAdd(&g_cur[i], 1);
        g_col[pos] = i;
    }
}

// ---------------- fp32 -> fp16 hi/lo conversion (layer-1 input only) --------
__global__ void k_cvt_a(const float4* __restrict__ A, int n4) {
    int i = blockIdx.x * blockDim.x + threadIdx.x;
    if (i >= n4) return;
    float4 v = A[i];
    __half hx = __float2half_rn(v.x);
    __half hy = __float2half_rn(v.y);
    __half hz = __float2half_rn(v.z);
    __half hw = __float2half_rn(v.w);
    __half2* oh = (__half2*)g_ah;
    __half2* ol = (__half2*)g_al;
    oh[2 * i]     = __halves2half2(hx, hy);
    oh[2 * i + 1] = __halves2half2(hz, hw);
    ol[2 * i]     = __halves2half2(__float2half_rn(v.x - __half2float(hx)),
                                   __float2half_rn(v.y - __half2float(hy)));
    ol[2 * i + 1] = __halves2half2(__float2half_rn(v.z - __half2float(hz)),
                                   __float2half_rn(v.w - __half2float(hw)));
}

// W [K, 256] fp32 -> Wt fp16 [256, K] via coalesced smem-tile transpose
__global__ void k_cvt_w(const float* __restrict__ W, int K) {
    __shared__ float t[32][33];
    int k0 = blockIdx.x * 32, n0 = blockIdx.y * 32;
    int tx = threadIdx.x, ty = threadIdx.y;   // (32, 8)
#pragma unroll
    for (int i = 0; i < 4; i++)
        t[ty + 8 * i][tx] = W[(size_t)(k0 + ty + 8 * i) * DHH + n0 + tx];
    __syncthreads();
#pragma unroll
    for (int i = 0; i < 4; i++)
        g_bh[(size_t)(n0 + ty + 8 * i) * K + k0 + tx] = __float2half_rn(t[tx][ty + 8 * i]);
}

__global__ void k_zero_sd() {
    int i = blockIdx.x * blockDim.x + threadIdx.x;
    if (i < NN) { g_sv[i] = 0.f; g_dv[i] = 0.f; }
}

// ---------------- HMMA fp16 GEMM: h[M,256] = A[M,K] @ Wt^T ------------------
// mma.sync m16n8k16 fp16, 2-pass hi/lo on A. CTA tile 128x128, 8 warps.
// B resident full-K; A via cp.async double buffering, ONE sync per k-iter:
//   cp_wait<0>; sync; prefetch(c+1) (overlaps compute); compute(c).
__device__ __forceinline__ uint32_t smem_u32(const void* p) {
    uint32_t a;
    asm("{ .reg .u64 t; cvta.to.shared.u64 t, %1; cvt.u32.u64 %0, t; }" : "=r"(a) : "l"(p));
    return a;
}
__device__ __forceinline__ void ldm_x4(uint32_t* r, uint32_t addr) {
    asm volatile("ldmatrix.sync.aligned.m8n8.x4.shared.b16 {%0,%1,%2,%3}, [%4];"
                 : "=r"(r[0]), "=r"(r[1]), "=r"(r[2]), "=r"(r[3]) : "r"(addr));
}
__device__ __forceinline__ void mma16816(float* c, const uint32_t* a, uint32_t b0, uint32_t b1) {
    asm volatile("mma.sync.aligned.m16n8k16.row.col.f32.f16.f16.f32 "
                 "{%0,%1,%2,%3}, {%4,%5,%6,%7}, {%8,%9}, {%0,%1,%2,%3};"
                 : "+f"(c[0]), "+f"(c[1]), "+f"(c[2]), "+f"(c[3])
                 : "r"(a[0]), "r"(a[1]), "r"(a[2]), "r"(a[3]), "r"(b0), "r"(b1));
}
__device__ __forceinline__ void cp16(uint32_t dst, const void* src) {
    asm volatile("cp.async.cg.shared.global [%0], [%1], 16;" :: "r"(dst), "l"(src) : "memory");
}
#define CP_COMMIT() asm volatile("cp.async.commit_group;" ::: "memory")
template <int N> __device__ __forceinline__ void cp_wait() {
    asm volatile("cp.async.wait_group %0;" :: "n"(N) : "memory");
}

#define ASTR 80      // A row stride bytes (32 fp16 + 8 pad)
#define ABUF 10240   // one A buffer (128 rows * 80)

__global__ __launch_bounds__(256, 2) void k_gemm_mma(
    const __half* __restrict__ Ah, const __half* __restrict__ Al,
    const __half* __restrict__ Bh,
    __half* __restrict__ C, const float* __restrict__ asrc, const float* __restrict__ adst,
    int M, int K)
{
    extern __shared__ char smem[];
    const int BSTR = 2 * K + 16;              // B row stride bytes (odd multiple of 16)
    // layout: [Ah0|Al0|Ah1|Al1|B|av|dv]
    char* sB = smem + 4 * ABUF;
    float* sAv = (float*)(sB + 128 * BSTR);
    float* sDv = sAv + DHH;

    int tid = threadIdx.x;
    int wid = tid >> 5, lane = tid & 31;
    int warp_m = wid >> 1, warp_n = wid & 1;
    int group = lane >> 2, tq = lane & 3;
    int m0 = blockIdx.y * 128;
    int n0 = blockIdx.x * 128;

    uint32_t sbase = smem_u32(smem);

    // per-thread A staging coords (2 chunks of 16B per buffer-half)
    int st_r[2], st_c[2];
#pragma unroll
    for (int l = 0; l < 2; l++) {
        int idx = tid + l * 256;
        st_r[l] = idx >> 2;
        st_c[l] = idx & 3;
    }

    // issue first A tile (hi+lo) via cp.async
#pragma unroll
    for (int l = 0; l < 2; l++) {
        int grow = m0 + st_r[l];
        if (grow > M - 1) grow = M - 1;     // clamp; OOB rows discarded in epilogue
        size_t src = (size_t)grow * K + st_c[l] * 8;
        uint32_t dst = sbase + st_r[l] * ASTR + st_c[l] * 16;
        cp16(dst, Ah + src);
        cp16(dst + ABUF, Al + src);
    }
    CP_COMMIT();

    sAv[tid] = asrc[tid];
    sDv[tid] = adst[tid];

    // B resident load (overlaps with in-flight cp.async)
    {
        int kc8 = K >> 3;
        for (int idx = tid; idx < 128 * kc8; idx += 256) {
            int n = idx / kc8, c = idx - n * kc8;
            *(uint4*)(sB + n * BSTR + c * 16) = *(const uint4*)(Bh + (size_t)(n0 + n) * K + c * 8);
        }
    }

    float acc[2][8][4];
#pragma unroll
    for (int mt = 0; mt < 2; mt++)
#pragma unroll
        for (int nt = 0; nt < 8; nt++)
#pragma unroll
            for (int q = 0; q < 4; q++) acc[mt][nt][q] = 0.f;

    uint32_t sb_h = smem_u32(sB);
    int a_row = warp_m * 32 + (lane & 15);
    int a_kh = ((lane >> 4) & 1) * 8;
    int b_n = warp_n * 64 + (lane & 7) + ((lane >> 4) & 1) * 8;
    int b_kh = ((lane >> 3) & 1) * 8;

    const int NCH = K >> 5;
    for (int c = 0; c < NCH; c++) {
        cp_wait<0>();        // buffer c fully landed
        __syncthreads();     // visibility + all warps done reading buffer (c-1)&1

        if (c + 1 < NCH) {   // prefetch next tile into the just-freed buffer
            uint32_t bufo = (uint32_t)((c + 1) & 1) * 2 * ABUF;
#pragma unroll
            for (int l = 0; l < 2; l++) {
                int grow = m0 + st_r[l];
                if (grow > M - 1) grow = M - 1;
                size_t src = (size_t)grow * K + (c + 1) * 32 + st_c[l] * 8;
                uint32_t dst = sbase + bufo + st_r[l] * ASTR + st_c[l] * 16;
                cp16(dst, Ah + src);
                cp16(dst + ABUF, Al + src);
            }
            CP_COMMIT();
        }

        uint32_t cbuf = (uint32_t)(c & 1) * 2 * ABUF;
        uint32_t sa_h = sbase + cbuf;
        uint32_t sa_l = sa_h + ABUF;
        int kt = c * 32;

#pragma unroll
        for (int kk = 0; kk < 32; kk += 16) {
            uint32_t ah[2][4], al[2][4], bh[4][4];
#pragma unroll
            for (int mt = 0; mt < 2; mt++) {
                uint32_t off = (uint32_t)(a_row + mt * 16) * ASTR + (kk + a_kh) * 2;
                ldm_x4(ah[mt], sa_h + off);
                ldm_x4(al[mt], sa_l + off);
            }
#pragma unroll
            for (int np = 0; np < 4; np++) {
                uint32_t off = (uint32_t)(b_n + np * 16) * BSTR + (kt + kk + b_kh) * 2;
                ldm_x4(bh[np], sb_h + off);
            }
#pragma unroll
            for (int mt = 0; mt < 2; mt++)
#pragma unroll
                for (int nt = 0; nt < 8; nt++) {
                    uint32_t b0 = bh[nt >> 1][(nt & 1) * 2];
                    uint32_t b1 = bh[nt >> 1][(nt & 1) * 2 + 1];
                    mma16816(acc[mt][nt], ah[mt], b0, b1);   // a_hi * b
                    mma16816(acc[mt][nt], al[mt], b0, b1);   // a_lo * b
                }
        }
    }

    // ---- epilogue: store h (fp16) + fused fp32 s/d partial dot products ----
    float sp[2][2] = {{0.f, 0.f}, {0.f, 0.f}};
    float dp[2][2] = {{0.f, 0.f}, {0.f, 0.f}};
#pragma unroll
    for (int mt = 0; mt < 2; mt++) {
        int r0 = m0 + warp_m * 32 + mt * 16 + group;
#pragma unroll
        for (int nt = 0; nt < 8; nt++) {
            int col = n0 + warp_n * 64 + nt * 8 + tq * 2;
            float a0 = sAv[col], a1 = sAv[col + 1];
            float d0 = sDv[col], d1 = sDv[col + 1];
            sp[mt][0] += acc[mt][nt][0] * a0 + acc[mt][nt][1] * a1;
            sp[mt][1] += acc[mt][nt][2] * a0 + acc[mt][nt][3] * a1;
            dp[mt][0] += acc[mt][nt][0] * d0 + acc[mt][nt][1] * d1;
            dp[mt][1] += acc[mt][nt][2] * d0 + acc[mt][nt][3] * d1;
            if (r0 < M)
                *(__half2*)(C + (size_t)r0 * DHH + col) =
                    __halves2half2(__float2half_rn(acc[mt][nt][0]), __float2half_rn(acc[mt][nt][1]));
            if (r0 + 8 < M)
                *(__half2*)(C + (size_t)(r0 + 8) * DHH + col) =
                    __halves2half2(__float2half_rn(acc[mt][nt][2]), __float2half_rn(acc[mt][nt][3]));
        }
    }
#pragma unroll
    for (int off = 1; off <= 2; off <<= 1) {
#pragma unroll
        for (int mt = 0; mt < 2; mt++)
#pragma unroll
            for (int rh = 0; rh < 2; rh++) {
                sp[mt][rh] += __shfl_xor_sync(0xffffffffu, sp[mt][rh], off);
                dp[mt][rh] += __shfl_xor_sync(0xffffffffu, dp[mt][rh], off);
            }
    }
    if (tq == 0) {
#pragma unroll
        for (int mt = 0; mt < 2; mt++) {
            int r0 = m0 + warp_m * 32 + mt * 16 + group;
            if (r0 < M)     { atomicAdd(&g_sv[r0], sp[mt][0]);     atomicAdd(&g_dv[r0], dp[mt][0]); }
            if (r0 + 8 < M) { atomicAdd(&g_sv[r0 + 8], sp[mt][1]); atomicAdd(&g_dv[r0 + 8], dp[mt][1]); }
        }
    }
}

// ---------------- softmax stats (single pass, one warp per node) ------------
// writes g_stat[node] = (max, 1/denominator); alpha computed inline in k_aggr.
__global__ __launch_bounds__(256) void k_stats() {
    int node = blockIdx.x * 8 + (threadIdx.x >> 5);
    int lane = threadIdx.x & 31;
    if (node >= NN) return;
    int beg = g_rowptr[node];
    int end = g_rowptr[node + 1];
    float di = g_dv[node];

    float m = -1e30f, den = 0.f;
    for (int j = beg + lane; j < end; j += 32) {
        float e = g_sv[g_col[j]] + di;
        e = (e > 0.f) ? e : 0.2f * e;
        if (e > m) { den *= __expf(m - e); m = e; }
        den += __expf(e - m);
    }
#pragma unroll
    for (int off = 16; off; off >>= 1) {
        float m2 = __shfl_xor_sync(0xffffffffu, m, off);
        float d2 = __shfl_xor_sync(0xffffffffu, den, off);
        float M = fmaxf(m, m2);
        den = den * __expf(m - M) + d2 * __expf(m2 - M);
        m = M;
    }
    if (lane == 0) g_stat[node] = make_float2(m, 1.0f / den);
}

// ---------------- weighted aggregation (half2 gather, inline alpha) ---------
// one 128-thread block per node; thread tid owns features 2*tid, 2*tid+1.
// alpha recomputed per thread from broadcast sv[col] loads (uniform per block).
template <bool POOL>
__global__ __launch_bounds__(128) void k_aggr(const float* __restrict__ bias) {
    int i = blockIdx.x;
    int tid = threadIdx.x;
    int beg = g_rowptr[i];
    int end = g_rowptr[i + 1];
    int f2 = tid * 2;
    float di = g_dv[i];
    float2 st = g_stat[i];
    float m = st.x, inv = st.y;

    float ax = 0.f, ay = 0.f;
    int j = beg;
    for (; j + 4 <= end; j += 4) {
        int c0 = g_col[j], c1 = g_col[j + 1], c2 = g_col[j + 2], c3 = g_col[j + 3];
        float e0 = g_sv[c0] + di, e1 = g_sv[c1] + di, e2 = g_sv[c2] + di, e3 = g_sv[c3] + di;
        e0 = (e0 > 0.f) ? e0 : 0.2f * e0;
        e1 = (e1 > 0.f) ? e1 : 0.2f * e1;
        e2 = (e2 > 0.f) ? e2 : 0.2f * e2;
        e3 = (e3 > 0.f) ? e3 : 0.2f * e3;
        float a0 = __expf(e0 - m) * inv, a1 = __expf(e1 - m) * inv;
        float a2 = __expf(e2 - m) * inv, a3 = __expf(e3 - m) * inv;
        float2 f0 = __half22float2(*(const __half2*)(g_hh + (size_t)c0 * DHH + f2));
        float2 f1 = __half22float2(*(const __half2*)(g_hh + (size_t)c1 * DHH + f2));
        float2 fq2 = __half22float2(*(const __half2*)(g_hh + (size_t)c2 * DHH + f2));
        float2 f3 = __half22float2(*(const __half2*)(g_hh + (size_t)c3 * DHH + f2));
        ax += a0 * f0.x + a1 * f1.x + a2 * fq2.x + a3 * f3.x;
        ay += a0 * f0.y + a1 * f1.y + a2 * fq2.y + a3 * f3.y;
    }
    for (; j < end; j++) {
        int c = g_col[j];
        float e = g_sv[c] + di;
        e = (e > 0.f) ? e : 0.2f * e;
        float a = __expf(e - m) * inv;
        float2 f = __half22float2(*(const __half2*)(g_hh + (size_t)c * DHH + f2));
        ax += a * f.x;
        ay += a * f.y;
    }

    float2 b = *(const float2*)(bias + f2);
    float vx = fmaxf(ax + b.x, 0.f);
    float vy = fmaxf(ay + b.y, 0.f);
    size_t idx = (size_t)i * DHH + f2;
    if (POOL) *(float2*)(g_f + idx) = make_float2(vx, vy);
    __half hx = __float2half_rn(vx), hy = __float2half_rn(vy);
    *(__half2*)(g_ah + idx) = __halves2half2(hx, hy);
    *(__half2*)(g_al + idx) = __halves2half2(__float2half_rn(vx - __half2float(hx)),
                                             __float2half_rn(vy - __half2float(hy)));
}

// ---------------- pooling ---------------------------------------------------
__global__ void k_pool(const void* __restrict__ batch) {
    __shared__ int sb[64];
    int base = blockIdx.x * 64;
    int tid = threadIdx.x;
    if (tid < 64) sb[tid] = (base + tid < NN) ? ld_idx(batch, base + tid) : -1;
    __syncthreads();
    float acc = 0.f;
    int cur = -1;
    for (int q = 0; q < 64; q++) {
        int g = sb[q];
        if (g < 0) break;
        if (g != cur) {
            if (cur >= 0) atomicAdd(&g_pool[cur * DHH + tid], acc);
            acc = 0.f; cur = g;
        }
        acc += g_f[(size_t)(base + q) * DHH + tid];
    }
    if (cur >= 0) atomicAdd(&g_pool[cur * DHH + tid], acc);
}

// ---------------- final FC --------------------------------------------------
__global__ void k_fc(const float* __restrict__ fcW, const float* __restrict__ fcb,
                     float* __restrict__ out) {
    int g = blockIdx.x;
    int o = threadIdx.x;
    float acc = fcb[o];
    for (int f = 0; f < DHH; f++)
        acc += g_pool[g * DHH + f] * fcW[f * DOUTT + o];
    out[g * DOUTT + o] = acc;
}

// ---------------- launch ----------------------------------------------------
extern "C" void kernel_launch(void* const* d_in, const int* in_sizes, int n_in,
                              void* d_out, int out_size) {
    const float* x = (const float*)d_in[0];
    const void* ei = d_in[1];
    const void* batch = d_in[2];
    const float* W[3]    = {(const float*)d_in[3], (const float*)d_in[7],  (const float*)d_in[11]};
    const float* asrc[3] = {(const float*)d_in[4], (const float*)d_in[8],  (const float*)d_in[12]};
    const float* adst[3] = {(const float*)d_in[5], (const float*)d_in[9],  (const float*)d_in[13]};
    const float* bias[3] = {(const float*)d_in[6], (const float*)d_in[10], (const float*)d_in[14]};
    const float* fcW = (const float*)d_in[15];
    const float* fcb = (const float*)d_in[16];
    float* out = (float*)d_out;

    void *hp = nullptr, *ahp = nullptr, *alp = nullptr, *bhp = nullptr;
    cudaGetSymbolAddress(&hp, g_hh);
    cudaGetSymbolAddress(&ahp, g_ah);
    cudaGetSymbolAddress(&alp, g_al);
    cudaGetSymbolAddress(&bhp, g_bh);
    __half* hbuf = (__half*)hp;

    const int SMEM_MMA = 4 * ABUF + 128 * (2 * DHH + 16) + 2048;   // K=256: 110592
    cudaFuncSetAttribute(k_gemm_mma, cudaFuncAttributeMaxDynamicSharedMemorySize, SMEM_MMA);

    auto run_gemm = [&](int l, int K) {
        int smem = 4 * ABUF + 128 * (2 * K + 16) + 2048;
        dim3 grid(DHH / 128, (NN + 127) / 128);
        k_gemm_mma<<<grid, 256, smem>>>(
            (const __half*)ahp, (const __half*)alp, (const __half*)bhp,
            hbuf, asrc[l], adst[l], NN, K);
    };

    // Layer-1 prologue ordered so k_gemm_mma is the 4th launch (ncu window).
    k_zero_sd<<<(NN + 255) / 256, 256>>>();                                // 1
    k_cvt_a<<<(NN * DINN / 4 + 255) / 256, 256>>>((const float4*)x, NN * DINN / 4);  // 2
    {
        dim3 tgrid(DINN / 32, DHH / 32);
        k_cvt_w<<<tgrid, dim3(32, 8)>>>(W[0], DINN);                       // 3
    }
    run_gemm(0, DINN);                                                      // 4

    // CSR build (needed before the first aggregation)
    k_detect<<<1, 256>>>((const int*)ei);
    k_init_cnt<<<(NN + 255) / 256, 256>>>();
    k_hist<<<(EE + 255) / 256, 256>>>(ei);
    k_chunk_sum<<<NCHUNK, 1024>>>();
    k_scan_chunks<<<1, 1>>>();
    k_local_scan<<<NCHUNK, 1024>>>();
    k_scatter<<<(TOTE + 255) / 256, 256>>>(ei);

    k_stats<<<(NN + 7) / 8, 256>>>();
    k_aggr<false><<<NN, 128>>>(bias[0]);

    for (int l = 1; l < 3; l++) {
        dim3 tgrid(DHH / 32, DHH / 32);
        k_cvt_w<<<tgrid, dim3(32, 8)>>>(W[l], DHH);
        k_zero_sd<<<(NN + 255) / 256, 256>>>();
        run_gemm(l, DHH);
        k_stats<<<(NN + 7) / 8, 256>>>();
        if (l == 2) k_aggr<true><<<NN, 128>>>(bias[l]);
        else        k_aggr<false><<<NN, 128>>>(bias[l]);
    }

    k_pool<<<(NN + 63) / 64, 256>>>(batch);
    k_fc<<<GGG, DOUTT>>>(fcW, fcb, out);
}

// round 17
// speedup vs baseline: 1.2064x; 1.2064x over previous
#include <cuda_runtime.h>
#include <cuda_fp16.h>
#include <cstdint>

#define NN   50000
#define EE   800000
#define DINN 128
#define DHH  256
#define DOUTT 64
#define GGG  64
#define TOTE (EE + NN)
#define NCHUNK 49   // ceil(NN/1024)

// ---------------- scratch (static device globals) ---------------------------
__device__ __align__(16) __half g_hh[(size_t)NN * DHH]; // GEMM output h (fp16)
__device__ __align__(16) float g_f[(size_t)NN * DHH];   // aggregated (last layer, for pool)
__device__ __align__(16) __half g_ah[(size_t)NN * DHH]; // A hi (fp16)
__device__ __align__(16) __half g_al[(size_t)NN * DHH]; // A lo (fp16)
__device__ __align__(16) __half g_bh[DHH * DHH];        // Wt fp16 [256][K]
__device__ float g_sv[NN];
__device__ float g_dv[NN];
__device__ float g_alpha[TOTE];
__device__ float g_pool[GGG * DHH];
__device__ int   g_cnt[NN];
__device__ int   g_rowptr[NN + 1];
__device__ int   g_cur[NN];
__device__ int   g_col[TOTE];
__device__ int   g_csum[NCHUNK];
__device__ int   g_i32;      // 1 => index tensors are int32, 0 => int64

// ---------------- dtype-agnostic index load ---------------------------------
__device__ __forceinline__ int ld_idx(const void* p, long i) {
    return g_i32 ? ((const int*)p)[i] : (int)((const long long*)p)[i];
}

__global__ void k_detect(const int* __restrict__ ei32) {
    __shared__ int any;
    if (threadIdx.x == 0) any = 0;
    __syncthreads();
    if (ei32[2 * threadIdx.x + 1] != 0) atomicOr(&any, 1);
    __syncthreads();
    if (threadIdx.x == 0) g_i32 = any;
}

// ---------------- CSR build -------------------------------------------------
__global__ void k_init_cnt() {
    int i = blockIdx.x * blockDim.x + threadIdx.x;
    if (i < NN) g_cnt[i] = 1;   // self-loop
}

__global__ void k_hist(const void* __restrict__ ei) {
    int e = blockIdx.x * blockDim.x + threadIdx.x;
    if (e < EE) atomicAdd(&g_cnt[ld_idx(ei, (long)EE + e)], 1);
}

__global__ void k_chunk_sum() {
    __shared__ int sr[1024];
    int tid = threadIdx.x;
    int i = blockIdx.x * 1024 + tid;
    sr[tid] = (i < NN) ? g_cnt[i] : 0;
    __syncthreads();
    for (int off = 512; off; off >>= 1) {
        if (tid < off) sr[tid] += sr[tid + off];
        __syncthreads();
    }
    if (tid == 0) g_csum[blockIdx.x] = sr[0];
}

__global__ void k_scan_chunks() {
    int run = 0;
    for (int c = 0; c < NCHUNK; c++) {
        int t = g_csum[c];
        g_csum[c] = run;
        run += t;
    }
    g_rowptr[NN] = TOTE;
}

__global__ void k_local_scan() {
    __shared__ int ss[1024];
    int tid = threadIdx.x;
    int i = blockIdx.x * 1024 + tid;
    int v = (i < NN) ? g_cnt[i] : 0;
    ss[tid] = v;
    __syncthreads();
    for (int off = 1; off < 1024; off <<= 1) {
        int add = (tid >= off) ? ss[tid - off] : 0;
        __syncthreads();
        ss[tid] += add;
        __syncthreads();
    }
    if (i < NN) {
        int rp = g_csum[blockIdx.x] + ss[tid] - v;   // exclusive
        g_rowptr[i] = rp;
        g_cur[i] = rp;
    }
}

__global__ void k_scatter(const void* __restrict__ ei) {
    int idx = blockIdx.x * blockDim.x + threadIdx.x;
    if (idx < GGG * DHH) g_pool[idx] = 0.f;     // fold pool zeroing in
    if (idx < EE) {
        int src = ld_idx(ei, idx);
        int dst = ld_idx(ei, (long)EE + idx);
        int pos = atomicAdd(&g_cur[dst], 1);
        g_col[pos] = src;
    } else if (idx < TOTE) {
        int i = idx - EE;
        int pos = atomicAdd(&g_cur[i], 1);
        g_col[pos] = i;
    }
}

// ---------------- fp32 -> fp16 hi/lo conversion (layer-1 input only) --------
// also zeroes g_sv/g_dv ahead of the layer-1 GEMM epilogue atomics.
__global__ void k_cvt_a(const float4* __restrict__ A, int n4) {
    int i = blockIdx.x * blockDim.x + threadIdx.x;
    if (i < NN) { g_sv[i] = 0.f; g_dv[i] = 0.f; }
    if (i >= n4) return;
    float4 v = A[i];
    __half hx = __float2half_rn(v.x);
    __half hy = __float2half_rn(v.y);
    __half hz = __float2half_rn(v.z);
    __half hw = __float2half_rn(v.w);
    __half2* oh = (__half2*)g_ah;
    __half2* ol = (__half2*)g_al;
    oh[2 * i]     = __halves2half2(hx, hy);
    oh[2 * i + 1] = __halves2half2(hz, hw);
    ol[2 * i]     = __halves2half2(__float2half_rn(v.x - __half2float(hx)),
                                   __float2half_rn(v.y - __half2float(hy)));
    ol[2 * i + 1] = __halves2half2(__float2half_rn(v.z - __half2float(hz)),
                                   __float2half_rn(v.w - __half2float(hw)));
}

// W [K, 256] fp32 -> Wt fp16 [256, K] via coalesced smem-tile transpose
__global__ void k_cvt_w(const float* __restrict__ W, int K) {
    __shared__ float t[32][33];
    int k0 = blockIdx.x * 32, n0 = blockIdx.y * 32;
    int tx = threadIdx.x, ty = threadIdx.y;   // (32, 8)
#pragma unroll
    for (int i = 0; i < 4; i++)
        t[ty + 8 * i][tx] = W[(size_t)(k0 + ty + 8 * i) * DHH + n0 + tx];
    __syncthreads();
#pragma unroll
    for (int i = 0; i < 4; i++)
        g_bh[(size_t)(n0 + ty + 8 * i) * K + k0 + tx] = __float2half_rn(t[tx][ty + 8 * i]);
}

// ---------------- HMMA fp16 GEMM: h[M,256] = A[M,K] @ Wt^T ------------------
// mma.sync m16n8k16 fp16, 2-pass hi/lo on A. CTA tile 128x128, 8 warps.
// B resident full-K; A via cp.async double buffering (R11-proven loop shape).
__device__ __forceinline__ uint32_t smem_u32(const void* p) {
    uint32_t a;
    asm("{ .reg .u64 t; cvta.to.shared.u64 t, %1; cvt.u32.u64 %0, t; }" : "=r"(a) : "l"(p));
    return a;
}
__device__ __forceinline__ void ldm_x4(uint32_t* r, uint32_t addr) {
    asm volatile("ldmatrix.sync.aligned.m8n8.x4.shared.b16 {%0,%1,%2,%3}, [%4];"
                 : "=r"(r[0]), "=r"(r[1]), "=r"(r[2]), "=r"(r[3]) : "r"(addr));
}
__device__ __forceinline__ void mma16816(float* c, const uint32_t* a, uint32_t b0, uint32_t b1) {
    asm volatile("mma.sync.aligned.m16n8k16.row.col.f32.f16.f16.f32 "
                 "{%0,%1,%2,%3}, {%4,%5,%6,%7}, {%8,%9}, {%0,%1,%2,%3};"
                 : "+f"(c[0]), "+f"(c[1]), "+f"(c[2]), "+f"(c[3])
                 : "r"(a[0]), "r"(a[1]), "r"(a[2]), "r"(a[3]), "r"(b0), "r"(b1));
}
__device__ __forceinline__ void cp16(uint32_t dst, const void* src) {
    asm volatile("cp.async.cg.shared.global [%0], [%1], 16;" :: "r"(dst), "l"(src) : "memory");
}
#define CP_COMMIT() asm volatile("cp.async.commit_group;" ::: "memory")
template <int N> __device__ __forceinline__ void cp_wait() {
    asm volatile("cp.async.wait_group %0;" :: "n"(N) : "memory");
}

#define ASTR 80      // A row stride bytes (32 fp16 + 8 pad)
#define ABUF 10240   // one A buffer (128 rows * 80)

__global__ __launch_bounds__(256, 2) void k_gemm_mma(
    const __half* __restrict__ Ah, const __half* __restrict__ Al,
    const __half* __restrict__ Bh,
    __half* __restrict__ C, const float* __restrict__ asrc, const float* __restrict__ adst,
    int M, int K)
{
    extern __shared__ char smem[];
    const int BSTR = 2 * K + 16;              // B row stride bytes (odd multiple of 16)
    // layout: [Ah0|Al0|Ah1|Al1|B|av|dv]
    char* sB = smem + 4 * ABUF;
    float* sAv = (float*)(sB + 128 * BSTR);
    float* sDv = sAv + DHH;

    int tid = threadIdx.x;
    int wid = tid >> 5, lane = tid & 31;
    int warp_m = wid >> 1, warp_n = wid & 1;
    int group = lane >> 2, tq = lane & 3;
    int m0 = blockIdx.y * 128;
    int n0 = blockIdx.x * 128;

    uint32_t sbase = smem_u32(smem);

    // per-thread A staging coords (2 chunks of 16B per buffer-half)
    int st_r[2], st_c[2];
#pragma unroll
    for (int l = 0; l < 2; l++) {
        int idx = tid + l * 256;
        st_r[l] = idx >> 2;
        st_c[l] = idx & 3;
    }

    // issue first A tile (hi+lo) via cp.async
#pragma unroll
    for (int l = 0; l < 2; l++) {
        int grow = m0 + st_r[l];
        if (grow > M - 1) grow = M - 1;     // clamp; OOB rows discarded in epilogue
        size_t src = (size_t)grow * K + st_c[l] * 8;
        uint32_t dst = sbase + st_r[l] * ASTR + st_c[l] * 16;
        cp16(dst, Ah + src);
        cp16(dst + ABUF, Al + src);
    }
    CP_COMMIT();

    sAv[tid] = asrc[tid];
    sDv[tid] = adst[tid];

    // B resident load (overlaps with in-flight cp.async)
    {
        int kc8 = K >> 3;
        for (int idx = tid; idx < 128 * kc8; idx += 256) {
            int n = idx / kc8, c = idx - n * kc8;
            *(uint4*)(sB + n * BSTR + c * 16) = *(const uint4*)(Bh + (size_t)(n0 + n) * K + c * 8);
        }
    }

    float acc[2][8][4];
#pragma unroll
    for (int mt = 0; mt < 2; mt++)
#pragma unroll
        for (int nt = 0; nt < 8; nt++)
#pragma unroll
            for (int q = 0; q < 4; q++) acc[mt][nt][q] = 0.f;

    uint32_t sb_h = smem_u32(sB);
    int a_row = warp_m * 32 + (lane & 15);
    int a_kh = ((lane >> 4) & 1) * 8;
    int b_n = warp_n * 64 + (lane & 7) + ((lane >> 4) & 1) * 8;
    int b_kh = ((lane >> 3) & 1) * 8;

    const int NCH = K >> 5;
    for (int c = 0; c < NCH; c++) {
        if (c + 1 < NCH) {
            uint32_t bufo = (uint32_t)((c + 1) & 1) * 2 * ABUF;
#pragma unroll
            for (int l = 0; l < 2; l++) {
                int grow = m0 + st_r[l];
                if (grow > M - 1) grow = M - 1;
                size_t src = (size_t)grow * K + (c + 1) * 32 + st_c[l] * 8;
                uint32_t dst = sbase + bufo + st_r[l] * ASTR + st_c[l] * 16;
                cp16(dst, Ah + src);
                cp16(dst + ABUF, Al + src);
            }
            CP_COMMIT();
            cp_wait<1>();
        } else {
            cp_wait<0>();
        }
        __syncthreads();

        uint32_t cbuf = (uint32_t)(c & 1) * 2 * ABUF;
        uint32_t sa_h = sbase + cbuf;
        uint32_t sa_l = sa_h + ABUF;
        int kt = c * 32;

#pragma unroll
        for (int kk = 0; kk < 32; kk += 16) {
            uint32_t ah[2][4], al[2][4], bh[4][4];
#pragma unroll
            for (int mt = 0; mt < 2; mt++) {
                uint32_t off = (uint32_t)(a_row + mt * 16) * ASTR + (kk + a_kh) * 2;
                ldm_x4(ah[mt], sa_h + off);
                ldm_x4(al[mt], sa_l + off);
            }
#pragma unroll
            for (int np = 0; np < 4; np++) {
                uint32_t off = (uint32_t)(b_n + np * 16) * BSTR + (kt + kk + b_kh) * 2;
                ldm_x4(bh[np], sb_h + off);
            }
#pragma unroll
            for (int mt = 0; mt < 2; mt++)
#pragma unroll
                for (int nt = 0; nt < 8; nt++) {
                    uint32_t b0 = bh[nt >> 1][(nt & 1) * 2];
                    uint32_t b1 = bh[nt >> 1][(nt & 1) * 2 + 1];
                    mma16816(acc[mt][nt], ah[mt], b0, b1);   // a_hi * b
                    mma16816(acc[mt][nt], al[mt], b0, b1);   // a_lo * b
                }
        }
        __syncthreads();   // all warps done reading before this buffer is re-staged
    }

    // ---- epilogue: store h (fp16) + fused fp32 s/d partial dot products ----
    float sp[2][2] = {{0.f, 0.f}, {0.f, 0.f}};
    float dp[2][2] = {{0.f, 0.f}, {0.f, 0.f}};
#pragma unroll
    for (int mt = 0; mt < 2; mt++) {
        int r0 = m0 + warp_m * 32 + mt * 16 + group;
#pragma unroll
        for (int nt = 0; nt < 8; nt++) {
            int col = n0 + warp_n * 64 + nt * 8 + tq * 2;
            float a0 = sAv[col], a1 = sAv[col + 1];
            float d0 = sDv[col], d1 = sDv[col + 1];
            sp[mt][0] += acc[mt][nt][0] * a0 + acc[mt][nt][1] * a1;
            sp[mt][1] += acc[mt][nt][2] * a0 + acc[mt][nt][3] * a1;
            dp[mt][0] += acc[mt][nt][0] * d0 + acc[mt][nt][1] * d1;
            dp[mt][1] += acc[mt][nt][2] * d0 + acc[mt][nt][3] * d1;
            if (r0 < M)
                *(__half2*)(C + (size_t)r0 * DHH + col) =
                    __halves2half2(__float2half_rn(acc[mt][nt][0]), __float2half_rn(acc[mt][nt][1]));
            if (r0 + 8 < M)
                *(__half2*)(C + (size_t)(r0 + 8) * DHH + col) =
                    __halves2half2(__float2half_rn(acc[mt][nt][2]), __float2half_rn(acc[mt][nt][3]));
        }
    }
#pragma unroll
    for (int off = 1; off <= 2; off <<= 1) {
#pragma unroll
        for (int mt = 0; mt < 2; mt++)
#pragma unroll
            for (int rh = 0; rh < 2; rh++) {
                sp[mt][rh] += __shfl_xor_sync(0xffffffffu, sp[mt][rh], off);
                dp[mt][rh] += __shfl_xor_sync(0xffffffffu, dp[mt][rh], off);
            }
    }
    if (tq == 0) {
#pragma unroll
        for (int mt = 0; mt < 2; mt++) {
            int r0 = m0 + warp_m * 32 + mt * 16 + group;
            if (r0 < M)     { atomicAdd(&g_sv[r0], sp[mt][0]);     atomicAdd(&g_dv[r0], dp[mt][0]); }
            if (r0 + 8 < M) { atomicAdd(&g_sv[r0 + 8], sp[mt][1]); atomicAdd(&g_dv[r0 + 8], dp[mt][1]); }
        }
    }
}

// ---------------- softmax stats + per-edge alpha (one warp per node) --------
// pass 1 gathers sv[col] once, stashing raw scores e into g_alpha (coalesced);
// pass 2 transforms g_alpha in place (coalesced read+write, no re-gather).
__global__ __launch_bounds__(256) void k_stats() {
    int node = blockIdx.x * 8 + (threadIdx.x >> 5);
    int lane = threadIdx.x & 31;
    if (node >= NN) return;
    int beg = g_rowptr[node];
    int end = g_rowptr[node + 1];
    float di = g_dv[node];

    float m = -1e30f, den = 0.f;
    for (int j = beg + lane; j < end; j += 32) {
        float e = g_sv[g_col[j]] + di;
        e = (e > 0.f) ? e : 0.2f * e;
        g_alpha[j] = e;                      // stash raw score
        if (e > m) { den *= __expf(m - e); m = e; }
        den += __expf(e - m);
    }
#pragma unroll
    for (int off = 16; off; off >>= 1) {
        float m2 = __shfl_xor_sync(0xffffffffu, m, off);
        float d2 = __shfl_xor_sync(0xffffffffu, den, off);
        float M = fmaxf(m, m2);
        den = den * __expf(m - M) + d2 * __expf(m2 - M);
        m = M;
    }
    float inv = 1.0f / den;
    for (int j = beg + lane; j < end; j += 32)
        g_alpha[j] = __expf(g_alpha[j] - m) * inv;   // coalesced transform
}

// ---------------- weighted aggregation (half2 gather, barrier-free) ---------
// one 128-thread block per node; thread tid owns features 2*tid, 2*tid+1.
// Also zeroes g_sv/g_dv for the NEXT layer's GEMM epilogue atomics (safe:
// k_stats of this layer has already consumed them).
template <bool POOL>
__global__ __launch_bounds__(128) void k_aggr(const float* __restrict__ bias) {
    int i = blockIdx.x;
    int tid = threadIdx.x;
    int beg = g_rowptr[i];
    int end = g_rowptr[i + 1];
    int f2 = tid * 2;

    if (tid == 0) { g_sv[i] = 0.f; g_dv[i] = 0.f; }

    float ax = 0.f, ay = 0.f;
    int j = beg;
    for (; j + 4 <= end; j += 4) {
        int c0 = g_col[j], c1 = g_col[j + 1], c2 = g_col[j + 2], c3 = g_col[j + 3];
        float a0 = g_alpha[j], a1 = g_alpha[j + 1], a2 = g_alpha[j + 2], a3 = g_alpha[j + 3];
        float2 f0 = __half22float2(*(const __half2*)(g_hh + (size_t)c0 * DHH + f2));
        float2 f1 = __half22float2(*(const __half2*)(g_hh + (size_t)c1 * DHH + f2));
        float2 fq2 = __half22float2(*(const __half2*)(g_hh + (size_t)c2 * DHH + f2));
        float2 f3 = __half22float2(*(const __half2*)(g_hh + (size_t)c3 * DHH + f2));
        ax += a0 * f0.x + a1 * f1.x + a2 * fq2.x + a3 * f3.x;
        ay += a0 * f0.y + a1 * f1.y + a2 * fq2.y + a3 * f3.y;
    }
    for (; j < end; j++) {
        float a = g_alpha[j];
        float2 f = __half22float2(*(const __half2*)(g_hh + (size_t)g_col[j] * DHH + f2));
        ax += a * f.x;
        ay += a * f.y;
    }

    float2 b = *(const float2*)(bias + f2);
    float vx = fmaxf(ax + b.x, 0.f);
    float vy = fmaxf(ay + b.y, 0.f);
    size_t idx = (size_t)i * DHH + f2;
    if (POOL) *(float2*)(g_f + idx) = make_float2(vx, vy);
    __half hx = __float2half_rn(vx), hy = __float2half_rn(vy);
    *(__half2*)(g_ah + idx) = __halves2half2(hx, hy);
    *(__half2*)(g_al + idx) = __halves2half2(__float2half_rn(vx - __half2float(hx)),
                                             __float2half_rn(vy - __half2float(hy)));
}

// ---------------- pooling ---------------------------------------------------
__global__ void k_pool(const void* __restrict__ batch) {
    __shared__ int sb[64];
    int base = blockIdx.x * 64;
    int tid = threadIdx.x;
    if (tid < 64) sb[tid] = (base + tid < NN) ? ld_idx(batch, base + tid) : -1;
    __syncthreads();
    float acc = 0.f;
    int cur = -1;
    for (int q = 0; q < 64; q++) {
        int g = sb[q];
        if (g < 0) break;
        if (g != cur) {
            if (cur >= 0) atomicAdd(&g_pool[cur * DHH + tid], acc);
            acc = 0.f; cur = g;
        }
        acc += g_f[(size_t)(base + q) * DHH + tid];
    }
    if (cur >= 0) atomicAdd(&g_pool[cur * DHH + tid], acc);
}

// ---------------- final FC --------------------------------------------------
__global__ void k_fc(const float* __restrict__ fcW, const float* __restrict__ fcb,
                     float* __restrict__ out) {
    int g = blockIdx.x;
    int o = threadIdx.x;
    float acc = fcb[o];
    for (int f = 0; f < DHH; f++)
        acc += g_pool[g * DHH + f] * fcW[f * DOUTT + o];
    out[g * DOUTT + o] = acc;
}

// ---------------- launch ----------------------------------------------------
extern "C" void kernel_launch(void* const* d_in, const int* in_sizes, int n_in,
                              void* d_out, int out_size) {
    const float* x = (const float*)d_in[0];
    const void* ei = d_in[1];
    const void* batch = d_in[2];
    const float* W[3]    = {(const float*)d_in[3], (const float*)d_in[7],  (const float*)d_in[11]};
    const float* asrc[3] = {(const float*)d_in[4], (const float*)d_in[8],  (const float*)d_in[12]};
    const float* adst[3] = {(const float*)d_in[5], (const float*)d_in[9],  (const float*)d_in[13]};
    const float* bias[3] = {(const float*)d_in[6], (const float*)d_in[10], (const float*)d_in[14]};
    const float* fcW = (const float*)d_in[15];
    const float* fcb = (const float*)d_in[16];
    float* out = (float*)d_out;

    void *hp = nullptr, *ahp = nullptr, *alp = nullptr, *bhp = nullptr;
    cudaGetSymbolAddress(&hp, g_hh);
    cudaGetSymbolAddress(&ahp, g_ah);
    cudaGetSymbolAddress(&alp, g_al);
    cudaGetSymbolAddress(&bhp, g_bh);
    __half* hbuf = (__half*)hp;

    const int SMEM_MMA = 4 * ABUF + 128 * (2 * DHH + 16) + 2048;   // K=256: 110592
    cudaFuncSetAttribute(k_gemm_mma, cudaFuncAttributeMaxDynamicSharedMemorySize, SMEM_MMA);

    auto run_gemm = [&](int l, int K) {
        int smem = 4 * ABUF + 128 * (2 * K + 16) + 2048;
        dim3 grid(DHH / 128, (NN + 127) / 128);
        k_gemm_mma<<<grid, 256, smem>>>(
            (const __half*)ahp, (const __half*)alp, (const __half*)bhp,
            hbuf, asrc[l], adst[l], NN, K);
    };

    // Layer-1 prologue ordered so k_gemm_mma is the 4th launch (ncu window).
    k_detect<<<1, 256>>>((const int*)ei);                                  // 1
    k_cvt_a<<<(NN * DINN / 4 + 255) / 256, 256>>>((const float4*)x, NN * DINN / 4);  // 2 (zeroes sv/dv too)
    {
        dim3 tgrid(DINN / 32, DHH / 32);
        k_cvt_w<<<tgrid, dim3(32, 8)>>>(W[0], DINN);                       // 3
    }
    run_gemm(0, DINN);                                                      // 4

    // CSR build (needed before the first aggregation)
    k_init_cnt<<<(NN + 255) / 256, 256>>>();
    k_hist<<<(EE + 255) / 256, 256>>>(ei);
    k_chunk_sum<<<NCHUNK, 1024>>>();
    k_scan_chunks<<<1, 1>>>();
    k_local_scan<<<NCHUNK, 1024>>>();
    k_scatter<<<(TOTE + 255) / 256, 256>>>(ei);

    k_stats<<<(NN + 7) / 8, 256>>>();
    k_aggr<false><<<NN, 128>>>(bias[0]);   // also zeroes sv/dv for layer 2

    for (int l = 1; l < 3; l++) {
        dim3 tgrid(DHH / 32, DHH / 32);
        k_cvt_w<<<tgrid, dim3(32, 8)>>>(W[l], DHH);
        run_gemm(l, DHH);
        k_stats<<<(NN + 7) / 8, 256>>>();
        if (l == 2) k_aggr<true><<<NN, 128>>>(bias[l]);
        else        k_aggr<false><<<NN, 128>>>(bias[l]);   // zeroes sv/dv for next layer
    }

    k_pool<<<(NN + 63) / 64, 256>>>(batch);
    k_fc<<<GGG, DOUTT>>>(fcW, fcb, out);
}